// round 14
// baseline (speedup 1.0000x reference)
#include <cuda_runtime.h>
#include <cuda.h>
#include <cuda_fp16.h>
#include <math.h>
#include <stdint.h>

// Problem dims
#define T_STEPS 128
#define BB      256
#define DIN     1024
#define HH      1024
#define NQ      8
#define DD      2048
#define NC      4112          // zf|zi|g|o|basef(8)|basei(8)
#define NPAD    4224          // 33 tiles of 128
#define NCTA    132

// ---------------- persistent device scratch ----------------
__device__ float g_Wall[(size_t)NC * DD];
__device__ float g_ball[NPAD];
__device__ __align__(256) __half g_Bpx[(size_t)NPAD * 1024];        // Wx fp16
__device__ __align__(256) __half g_Bph[(size_t)NPAD * 1024];        // Wh fp16
__device__ __align__(256) __half g_Xp[(size_t)T_STEPS * BB * 1024]; // fp16(X)
__device__ __align__(256) __half g_Hp[(size_t)BB * 1024];           // fp16(hx)
__device__ __align__(256) __half g_encf16[1024 * 1024];
__device__ __align__(256) __half g_enci16[1024 * 1024];
__device__ __align__(256) __half g_WqT[2048 * 1024];                // Wq^T fp16 [d][q]
__device__ float g_CXall[(size_t)T_STEPS * NPAD * BB];              // X-part C^T per t (+bias)
__device__ float g_CTh[(size_t)NPAD * BB];                          // H-part C^T
__device__ float g_CXT[HH * BB];                                    // cell state [h][b]
__device__ unsigned long long g_bar = 0;    // grid-barrier tickets (monotonic)
__device__ unsigned long long g_run = 0;    // replay-epoch tickets (monotonic)
__device__ unsigned long long g_xdone = 0;  // xpre tiles finished (monotonic)

// ============================================================
// common mma helpers
// ============================================================
__device__ __forceinline__ uint32_t smem_u32(const void* p) {
    uint32_t a;
    asm("{ .reg .u64 t; cvta.to.shared.u64 t, %1; cvt.u32.u64 %0, t; }" : "=r"(a) : "l"(p));
    return a;
}
__device__ __forceinline__ void cp_async16(uint32_t dst, const void* src) {
    asm volatile("cp.async.cg.shared.global [%0], [%1], 16;" :: "r"(dst), "l"(src));
}
__device__ __forceinline__ void ldmatrix_x4(uint32_t& r0, uint32_t& r1,
                                            uint32_t& r2, uint32_t& r3, uint32_t a) {
    asm volatile("ldmatrix.sync.aligned.m8n8.x4.shared.b16 {%0,%1,%2,%3}, [%4];"
                 : "=r"(r0), "=r"(r1), "=r"(r2), "=r"(r3) : "r"(a));
}
__device__ __forceinline__ void mma_f16(float* c, const uint32_t* a,
                                        uint32_t b0, uint32_t b1) {
    asm volatile("mma.sync.aligned.m16n8k16.row.col.f32.f16.f16.f32 "
                 "{%0,%1,%2,%3}, {%4,%5,%6,%7}, {%8,%9}, {%0,%1,%2,%3};"
                 : "+f"(c[0]), "+f"(c[1]), "+f"(c[2]), "+f"(c[3])
                 : "r"(a[0]), "r"(a[1]), "r"(a[2]), "r"(a[3]), "r"(b0), "r"(b1));
}
__device__ __forceinline__ float sigf(float x) {
    float e = __expf(-x);
    return __fdividef(1.f, 1.f + e);
}

// ============================================================
// GEMM geometry: 64(M)x128(N) tile, K=1024, BK=32, 3-stage
// ============================================================
#define APITCH  40
#define A_ST    (64 * APITCH * 2)        // 5120
#define B_ST    (128 * APITCH * 2)       // 10240
#define STG_B   (A_ST + B_ST)            // 15360
#define PIPE_B  (3 * STG_B)              // 46080 per engine
#define GSMEM   (2 * PIPE_B)             // 92160: [H pipeline | xpre pipeline]
#define NTL     32

#define HBAR()  asm volatile("bar.sync 1, 256;" ::: "memory")   // H warps (4..11)
#define XBAR()  asm volatile("bar.sync 2, 128;" ::: "memory")   // xpre warps (0..3)

// H-GEMM: 8 warps (2Mx4N, warp 32x32), threads htid 0..255
__device__ __forceinline__ void gemm64(const __half* __restrict__ Asrc,
                                       const __half* __restrict__ Bsrc,
                                       float* __restrict__ Cdst,
                                       int m0, int n0, uint32_t sb, int tid)
{
    const int lane = tid & 31, wid = tid >> 5;
    const int wm = wid & 1, wn = wid >> 1;

    const int arow = tid >> 2, ach = tid & 3;
    const __half* gA = Asrc + (size_t)(m0 + arow) * 1024 + ach * 8;
    const uint32_t daB = sb + (arow * APITCH + ach * 8) * 2;
    const int brow = tid >> 1, bch = tid & 1;
    const __half* gB = Bsrc + (size_t)(n0 + brow) * 1024 + bch * 16;
    const uint32_t dbB = sb + A_ST + (brow * APITCH + bch * 16) * 2;

    float acc[2][4][4];
#pragma unroll
    for (int i = 0; i < 2; i++)
#pragma unroll
        for (int j = 0; j < 4; j++)
#pragma unroll
            for (int r = 0; r < 4; r++) acc[i][j][r] = 0.f;

    const uint32_t aA0 = sb + ((wm * 32 + (lane & 15)) * APITCH + (lane >> 4) * 8) * 2;
    const int brl = wn * 32 + (lane & 7) + ((lane >> 4) << 3);
    const uint32_t bA0 = sb + A_ST + (brl * APITCH + ((lane >> 3) & 1) * 8) * 2;

    auto issue = [&](int kt, int st) {
        cp_async16(daB + st * STG_B, gA + kt * 32);
        const uint32_t db = dbB + st * STG_B;
        const __half* gb = gB + kt * 32;
        cp_async16(db, gb);
        cp_async16(db + 16, gb + 8);
    };

#pragma unroll
    for (int s = 0; s < 2; s++) {
        issue(s, s);
        asm volatile("cp.async.commit_group;");
    }

    for (int kt = 0; kt < NTL; kt++) {
        asm volatile("cp.async.wait_group 1;");
        HBAR();
        if (kt + 2 < NTL) issue(kt + 2, (kt + 2) % 3);
        asm volatile("cp.async.commit_group;");

        const int st = kt % 3;
        const uint32_t aB = aA0 + st * STG_B;
        const uint32_t bB = bA0 + st * STG_B;
#pragma unroll
        for (int kk = 0; kk < 2; kk++) {
            uint32_t a[2][4], b[2][4];
#pragma unroll
            for (int mf = 0; mf < 2; mf++)
                ldmatrix_x4(a[mf][0], a[mf][1], a[mf][2], a[mf][3],
                            aB + (mf * 16 * APITCH + kk * 16) * 2);
#pragma unroll
            for (int nf = 0; nf < 2; nf++)
                ldmatrix_x4(b[nf][0], b[nf][1], b[nf][2], b[nf][3],
                            bB + (nf * 16 * APITCH + kk * 16) * 2);
#pragma unroll
            for (int mf = 0; mf < 2; mf++)
#pragma unroll
                for (int nf = 0; nf < 2; nf++) {
                    mma_f16(acc[mf][nf * 2 + 0], a[mf], b[nf][0], b[nf][1]);
                    mma_f16(acc[mf][nf * 2 + 1], a[mf], b[nf][2], b[nf][3]);
                }
        }
    }

#pragma unroll
    for (int mf = 0; mf < 2; mf++) {
        const int mb = m0 + wm * 32 + mf * 16 + (lane >> 2);
#pragma unroll
        for (int j = 0; j < 4; j++) {
            const int nb = n0 + wn * 32 + j * 8 + 2 * (lane & 3);
            Cdst[(size_t)nb * BB + mb]           = acc[mf][j][0];
            Cdst[(size_t)(nb + 1) * BB + mb]     = acc[mf][j][1];
            Cdst[(size_t)nb * BB + mb + 8]       = acc[mf][j][2];
            Cdst[(size_t)(nb + 1) * BB + mb + 8] = acc[mf][j][3];
        }
    }
}

__device__ __forceinline__ void grid_bar256(int htid) {
    HBAR();
    if (htid == 0) {
        __threadfence();
        unsigned long long t0 = atomicAdd(&g_bar, 1ULL);
        unsigned long long tgt = (t0 / (unsigned long long)NCTA + 1ULL) * (unsigned long long)NCTA;
        while (*((volatile unsigned long long*)&g_bar) < tgt) { __nanosleep(32); }
        __threadfence();
    }
    HBAR();
}

// ============================================================
// Persistent kernel: warps 0-3 = xpre engine, warps 4-11 = recurrence
// ============================================================
__global__ __launch_bounds__(384, 1) void persist_kernel(
    float* __restrict__ out,
    const float* __restrict__ wfw, const float* __restrict__ wfb,
    const float* __restrict__ wiw, const float* __restrict__ wib)
{
    extern __shared__ __align__(16) char smraw[];
    const uint32_t sb = smem_u32(smraw);
    __shared__ unsigned long long s_xbase;
    const int tid = threadIdx.x;
    const int n0 = blockIdx.x * 128, m0 = blockIdx.y * 64;
    const int cta = blockIdx.y * 33 + blockIdx.x;

    if (tid == 0) {
        unsigned long long rr = atomicAdd(&g_run, 1ULL);
        s_xbase = (rr / (unsigned long long)NCTA) *
                  (unsigned long long)NCTA * (unsigned long long)T_STEPS;
    }
    __syncthreads();                       // only CTA-wide sync; before specialization
    const unsigned long long xbase = s_xbase;

    if (tid < 128) {
        // ---------------- xpre engine (4 warps, low priority) ----------------
        const int t2 = tid, lane = tid & 31, wid2 = tid >> 5;
        const int wm2 = wid2 & 1, wn2 = wid2 >> 1;     // warp tile 32x64
        const uint32_t xb = sb + PIPE_B;

        const int arow = t2 >> 1, ach = t2 & 1;        // A: 2 thr/row, 32B each
        const uint32_t daB = xb + (arow * APITCH + ach * 16) * 2;
        const int brow = t2;                           // B: 1 thr/row, 64B
        const __half* gB = g_Bpx + (size_t)(n0 + brow) * 1024;
        const uint32_t dbB = xb + A_ST + (brow * APITCH) * 2;

        const uint32_t aA0 = xb + ((wm2 * 32 + (lane & 15)) * APITCH + (lane >> 4) * 8) * 2;
        const int brl = wn2 * 64 + (lane & 7) + ((lane >> 4) << 3);
        const uint32_t bA0 = xb + A_ST + (brl * APITCH + ((lane >> 3) & 1) * 8) * 2;

        for (int ts = 0; ts < T_STEPS; ts++) {
            const __half* gA = g_Xp + (size_t)ts * BB * 1024
                             + (size_t)(m0 + arow) * 1024 + ach * 16;

            auto issue = [&](int kt, int st) {
                const uint32_t da = daB + st * STG_B;
                const __half* ga = gA + kt * 32;
                cp_async16(da, ga);
                cp_async16(da + 16, ga + 8);
                const uint32_t db = dbB + st * STG_B;
                const __half* gb = gB + kt * 32;
#pragma unroll
                for (int j = 0; j < 4; j++) cp_async16(db + j * 16, gb + j * 8);
            };

            float acc[2][8][4];
#pragma unroll
            for (int i = 0; i < 2; i++)
#pragma unroll
                for (int j = 0; j < 8; j++)
#pragma unroll
                    for (int r = 0; r < 4; r++) acc[i][j][r] = 0.f;

#pragma unroll
            for (int s = 0; s < 2; s++) {
                issue(s, s);
                asm volatile("cp.async.commit_group;");
            }

            for (int kt = 0; kt < NTL; kt++) {
                asm volatile("cp.async.wait_group 1;");
                XBAR();
                if (kt + 2 < NTL) issue(kt + 2, (kt + 2) % 3);
                asm volatile("cp.async.commit_group;");

                const int st = kt % 3;
                const uint32_t aB = aA0 + st * STG_B;
                const uint32_t bB = bA0 + st * STG_B;
#pragma unroll
                for (int kk = 0; kk < 2; kk++) {
                    uint32_t a[2][4], b[4][4];
#pragma unroll
                    for (int mf = 0; mf < 2; mf++)
                        ldmatrix_x4(a[mf][0], a[mf][1], a[mf][2], a[mf][3],
                                    aB + (mf * 16 * APITCH + kk * 16) * 2);
#pragma unroll
                    for (int nf = 0; nf < 4; nf++)
                        ldmatrix_x4(b[nf][0], b[nf][1], b[nf][2], b[nf][3],
                                    bB + (nf * 16 * APITCH + kk * 16) * 2);
#pragma unroll
                    for (int mf = 0; mf < 2; mf++)
#pragma unroll
                        for (int nf = 0; nf < 4; nf++) {
                            mma_f16(acc[mf][nf * 2 + 0], a[mf], b[nf][0], b[nf][1]);
                            mma_f16(acc[mf][nf * 2 + 1], a[mf], b[nf][2], b[nf][3]);
                        }
                }
            }

            float* ct = g_CXall + (size_t)ts * NPAD * BB;
#pragma unroll
            for (int mf = 0; mf < 2; mf++) {
                const int mb = m0 + wm2 * 32 + mf * 16 + (lane >> 2);
#pragma unroll
                for (int q = 0; q < 8; q++) {
                    const int nb = n0 + wn2 * 64 + q * 8 + 2 * (lane & 3);
                    const float b0 = __ldg(&g_ball[nb]), b1 = __ldg(&g_ball[nb + 1]);
                    ct[(size_t)nb * BB + mb]           = acc[mf][q][0] + b0;
                    ct[(size_t)(nb + 1) * BB + mb]     = acc[mf][q][1] + b1;
                    ct[(size_t)nb * BB + mb + 8]       = acc[mf][q][2] + b0;
                    ct[(size_t)(nb + 1) * BB + mb + 8] = acc[mf][q][3] + b1;
                }
            }
            __threadfence();
            XBAR();
            if (t2 == 0) atomicAdd(&g_xdone, 1ULL);
        }
    } else {
        // ---------------- recurrence (8 warps, high priority) ----------------
        const int htid = tid - 128;          // 0..255
        for (int t = 0; t < T_STEPS; t++) {
            gemm64(g_Hp, g_Bph, g_CTh, m0, n0, sb, htid);
            grid_bar256(htid);

            // wait for X-part of step t chip-wide (replay-safe monotonic target)
            const unsigned long long tgt =
                xbase + (unsigned long long)NCTA * (unsigned long long)(t + 1);
            while (*((volatile unsigned long long*)&g_xdone) < tgt) { __nanosleep(64); }
            __threadfence();

            const float* cth = g_CTh;
            const float* ctx = g_CXall + (size_t)t * NPAD * BB;
            float* out_t = out + (size_t)t * BB * HH;
#pragma unroll 1
            for (int k = 0; k < 8; k++) {
                int id = cta * 256 + htid + k * (NCTA * 256);
                if (id >= BB * HH) break;
                int h = id >> 8, b = id & 255;
                auto rd = [&](int n) {
                    size_t p = (size_t)n * BB + b;
                    return cth[p] + ctx[p];
                };
                float f_pre, i_pre;
                if (h < NQ) {
                    float df[NQ], di[NQ];
                    f_pre = 0.f; i_pre = 0.f;
#pragma unroll
                    for (int i = 0; i < NQ; i++) {
                        float dot = rd(4096 + i) + __ldg(&wfb[i]);
#pragma unroll
                        for (int kk = 0; kk < NQ; kk++)
                            if (kk < i) dot += df[kk] * __ldg(&wfw[i * 1024 + kk]);
                        float v = tanhf(dot);
                        df[i] = v - rd(i);
                        if (i == h) f_pre = v;
                    }
#pragma unroll
                    for (int i = 0; i < NQ; i++) {
                        float dot = rd(4104 + i) + __ldg(&wib[i]);
#pragma unroll
                        for (int kk = 0; kk < NQ; kk++)
                            if (kk < i) dot += di[kk] * __ldg(&wiw[i * 1024 + kk]);
                        float v = tanhf(dot);
                        di[i] = v - rd(1024 + i);
                        if (i == h) i_pre = v;
                    }
                } else {
                    f_pre = rd(h);
                    i_pre = rd(1024 + h);
                }
                const float gg = tanhf(rd(2048 + h));
                const float o  = sigf(rd(3072 + h));
                const size_t p = (size_t)h * BB + b;
                const float c = sigf(f_pre) * g_CXT[p] + sigf(i_pre) * gg;
                g_CXT[p] = c;
                const float hv = o * tanhf(c);
                out_t[(size_t)b * HH + h] = hv;
                g_Hp[(size_t)b * 1024 + h] = __float2half(hv);
            }
            grid_bar256(htid);
        }
    }
}

// ============================================================
// prep: big fp16 GEMM (enc @ Wq), 256(M)x128(N), 8 warps 64x64
// ============================================================
#define XAP     40
#define XP_AST  (256 * XAP * 2)
#define XP_BST  (128 * XAP * 2)
#define XP_STG  (XP_AST + XP_BST)
#define XP_SMEM (4 * XP_STG)

struct Acc256 { float v[4][8][4]; };

__device__ __forceinline__ void big_mainloop(const __half* __restrict__ Asrc,
                                             const __half* __restrict__ Bsrc,
                                             int m0, int n0, uint32_t sb, int tid,
                                             Acc256& A)
{
    const int lane = tid & 31, wid = tid >> 5;
    const int wm = wid >> 1, wn = wid & 1;

    const __half* gA = Asrc + (size_t)(m0 + tid) * 1024;
    const uint32_t daB = sb + (tid * XAP) * 2;
    const int brow = tid >> 1, bch = tid & 1;
    const __half* gB = Bsrc + (size_t)(n0 + brow) * 1024 + bch * 16;
    const uint32_t dbB = sb + XP_AST + (brow * XAP + bch * 16) * 2;

    auto issue = [&](int kt, int st) {
        const uint32_t da = daB + st * XP_STG;
        const __half* ga = gA + kt * 32;
#pragma unroll
        for (int j = 0; j < 4; j++) cp_async16(da + j * 16, ga + j * 8);
        const uint32_t db = dbB + st * XP_STG;
        const __half* gb = gB + kt * 32;
        cp_async16(db, gb);
        cp_async16(db + 16, gb + 8);
    };

#pragma unroll
    for (int i = 0; i < 4; i++)
#pragma unroll
        for (int j = 0; j < 8; j++)
#pragma unroll
            for (int r = 0; r < 4; r++) A.v[i][j][r] = 0.f;

    const uint32_t aA0 = sb + ((wm * 64 + (lane & 15)) * XAP + (lane >> 4) * 8) * 2;
    const int brl = wn * 64 + (lane & 7) + ((lane >> 4) << 3);
    const uint32_t bA0 = sb + XP_AST + (brl * XAP + ((lane >> 3) & 1) * 8) * 2;

#pragma unroll
    for (int s = 0; s < 3; s++) {
        issue(s, s);
        asm volatile("cp.async.commit_group;");
    }

    for (int kt = 0; kt < 32; kt++) {
        asm volatile("cp.async.wait_group 2;");
        __syncthreads();
        if (kt + 3 < 32) issue(kt + 3, (kt + 3) & 3);
        asm volatile("cp.async.commit_group;");

        const int st = kt & 3;
        const uint32_t aB = aA0 + st * XP_STG;
        const uint32_t bB = bA0 + st * XP_STG;
#pragma unroll
        for (int kk = 0; kk < 2; kk++) {
            uint32_t a[4][4], b[4][4];
#pragma unroll
            for (int mf = 0; mf < 4; mf++)
                ldmatrix_x4(a[mf][0], a[mf][1], a[mf][2], a[mf][3],
                            aB + (mf * 16 * XAP + kk * 16) * 2);
#pragma unroll
            for (int nf = 0; nf < 4; nf++)
                ldmatrix_x4(b[nf][0], b[nf][1], b[nf][2], b[nf][3],
                            bB + (nf * 16 * XAP + kk * 16) * 2);
#pragma unroll
            for (int mf = 0; mf < 4; mf++)
#pragma unroll
                for (int nf = 0; nf < 4; nf++) {
                    mma_f16(A.v[mf][nf * 2 + 0], a[mf], b[nf][0], b[nf][1]);
                    mma_f16(A.v[mf][nf * 2 + 1], a[mf], b[nf][2], b[nf][3]);
                }
        }
    }
}

// grid (16, 4, 2): Wall rows [z*1024 .. +1024) = enc_z @ Wq
__global__ __launch_bounds__(256, 1) void prep_mma_kernel()
{
    extern __shared__ __align__(16) char smraw[];
    const uint32_t sb = smem_u32(smraw);
    const int tid = threadIdx.x, lane = tid & 31, wid = tid >> 5;
    const int wm = wid >> 1, wn = wid & 1;
    const int n0 = blockIdx.x * 128;
    const int m0 = blockIdx.y * 256;
    const int z  = blockIdx.z;

    Acc256 A;
    big_mainloop(z ? g_enci16 : g_encf16, g_WqT, m0, n0, sb, tid, A);

    float* Wdst = g_Wall + (size_t)(z * 1024 + m0) * DD;
#pragma unroll
    for (int mf = 0; mf < 4; mf++) {
        const int mb = wm * 64 + mf * 16 + (lane >> 2);
#pragma unroll
        for (int q = 0; q < 8; q++) {
            const int nb = n0 + wn * 64 + q * 8 + 2 * (lane & 3);
            Wdst[(size_t)mb * DD + nb]           = A.v[mf][q][0];
            Wdst[(size_t)mb * DD + nb + 1]       = A.v[mf][q][1];
            Wdst[(size_t)(mb + 8) * DD + nb]     = A.v[mf][q][2];
            Wdst[(size_t)(mb + 8) * DD + nb + 1] = A.v[mf][q][3];
        }
    }
}

// ============================================================
// small prep kernels
// ============================================================
__global__ void zero_cx_kernel() {
    int idx = blockIdx.x * blockDim.x + threadIdx.x;
    if (idx < HH * BB) g_CXT[idx] = 0.f;
}
__global__ void zero_hp_kernel() {
    int idx = blockIdx.x * blockDim.x + threadIdx.x;
    if (idx < BB * 1024) g_Hp[idx] = __float2half(0.f);
}
__global__ void copy_wuwo_kernel(const float* __restrict__ Wu, const float* __restrict__ Wo) {
    size_t idx = (size_t)blockIdx.x * blockDim.x + threadIdx.x;
    size_t total = (size_t)2 * 1024 * DD;
    if (idx < total) {
        float v = (idx < (size_t)1024 * DD) ? Wu[idx] : Wo[idx - (size_t)1024 * DD];
        g_Wall[(size_t)2048 * DD + idx] = v;
    }
}
__global__ void enc16_kernel(const float* __restrict__ encf, const float* __restrict__ enci) {
    int idx = blockIdx.x * blockDim.x + threadIdx.x;
    if (idx < 1024 * 1024) {
        g_encf16[idx] = __float2half(encf[idx]);
        g_enci16[idx] = __float2half(enci[idx]);
    }
}
__global__ void wqt_kernel(const float* __restrict__ Wq) {
    __shared__ float tile[32][33];
    int dx = blockIdx.x * 32, qy = blockIdx.y * 32;
    int tx = threadIdx.x, ty = threadIdx.y;
#pragma unroll
    for (int r = 0; r < 4; r++)
        tile[ty + r * 8][tx] = Wq[(size_t)(qy + ty + r * 8) * 2048 + dx + tx];
    __syncthreads();
#pragma unroll
    for (int r = 0; r < 4; r++)
        g_WqT[(size_t)(dx + ty + r * 8) * 1024 + qy + tx] =
            __float2half(tile[tx][ty + r * 8]);
}
__global__ void bias_enc_kernel(const float* __restrict__ encf, const float* __restrict__ enci,
                                const float* __restrict__ bq)
{
    int w = (blockIdx.x * blockDim.x + threadIdx.x) >> 5;
    int lane = threadIdx.x & 31;
    if (w >= 2048) return;
    const float* enc = (w < 1024) ? encf : enci;
    int row = w & 1023;
    float s = 0.f;
    for (int j = lane; j < 1024; j += 32) s += enc[row * 1024 + j] * bq[j];
#pragma unroll
    for (int o = 16; o > 0; o >>= 1) s += __shfl_xor_sync(0xFFFFFFFF, s, o);
    if (lane == 0) g_ball[w] = s;
}
__global__ void bias_copy_kernel(const float* __restrict__ bu, const float* __restrict__ bo) {
    int n = 2048 + blockIdx.x * blockDim.x + threadIdx.x;
    if (n < 3072) g_ball[n] = bu[n - 2048];
    else if (n < 4096) g_ball[n] = bo[n - 3072];
    else if (n >= 4112 && n < NPAD) g_ball[n] = 0.f;
}
__global__ void wb_rows_kernel(const float* __restrict__ wfw, const float* __restrict__ wiw) {
    int i16 = blockIdx.y;
    int d = blockIdx.x * 256 + threadIdx.x;
    int g = i16 >> 3, i = i16 & 7;
    const float* ww = g ? wiw : wfw;
    float s = 0.f;
    for (int j = 0; j < 1024; j++)
        s += __ldg(&ww[i * 1024 + j]) * g_Wall[(size_t)(g * 1024 + j) * DD + d];
    g_Wall[(size_t)(4096 + i16) * DD + d] = s;
}
__global__ void bias_wb_kernel(const float* __restrict__ wfw, const float* __restrict__ wiw) {
    int w = threadIdx.x >> 5, lane = threadIdx.x & 31;
    if (w >= 16) return;
    int g = w >> 3, i = w & 7;
    const float* ww = g ? wiw : wfw;
    const float* bb = g_ball + g * 1024;
    float s = 0.f;
    for (int j = lane; j < 1024; j += 32) s += ww[i * 1024 + j] * bb[j];
#pragma unroll
    for (int o = 16; o > 0; o >>= 1) s += __shfl_xor_sync(0xFFFFFFFF, s, o);
    if (lane == 0) g_ball[4096 + w] = s;
}
__global__ void bsplit_kernel() {
    size_t idx = (size_t)blockIdx.x * blockDim.x + threadIdx.x;
    if (idx >= (size_t)NPAD * 2048) return;
    int n = (int)(idx / 2048), c = (int)(idx % 2048);
    float v = (n < NC) ? g_Wall[(size_t)n * DD + c] : 0.f;
    if (c < 1024) g_Bpx[(size_t)n * 1024 + c] = __float2half(v);
    else          g_Bph[(size_t)n * 1024 + (c - 1024)] = __float2half(v);
}
__global__ void xprep_kernel(const float* __restrict__ X) {
    size_t idx = (size_t)blockIdx.x * blockDim.x + threadIdx.x;
    if (idx < (size_t)T_STEPS * BB * 1024)
        g_Xp[idx] = __float2half(X[idx]);
}
__global__ void tail_kernel(float* __restrict__ out) {
    int idx = blockIdx.x * blockDim.x + threadIdx.x;
    if (idx < BB * HH) {
        out[(size_t)T_STEPS * BB * HH + idx] = out[(size_t)(T_STEPS - 1) * BB * HH + idx];
        out[(size_t)T_STEPS * BB * HH + BB * HH + idx] =
            g_CXT[(size_t)(idx & 1023) * BB + (idx >> 10)];
    }
}

// ============================================================
// host
// ============================================================
extern "C" void kernel_launch(void* const* d_in, const int* in_sizes, int n_in,
                              void* d_out, int out_size)
{
    const float* X    = (const float*)d_in[0];
    const float* Wq   = (const float*)d_in[1];
    const float* bq   = (const float*)d_in[2];
    const float* encf = (const float*)d_in[3];
    const float* wfw  = (const float*)d_in[4];
    const float* wfb  = (const float*)d_in[5];
    const float* enci = (const float*)d_in[6];
    const float* wiw  = (const float*)d_in[7];
    const float* wib  = (const float*)d_in[8];
    const float* Wu   = (const float*)d_in[9];
    const float* bu   = (const float*)d_in[10];
    const float* Wo   = (const float*)d_in[11];
    const float* bo   = (const float*)d_in[12];
    float* out = (float*)d_out;

    static bool attr_done = false;
    if (!attr_done) {
        cudaFuncSetAttribute(persist_kernel, cudaFuncAttributeMaxDynamicSharedMemorySize, GSMEM);
        cudaFuncSetAttribute(prep_mma_kernel, cudaFuncAttributeMaxDynamicSharedMemorySize, XP_SMEM);
        attr_done = true;
    }

    // ---- prep ----
    zero_cx_kernel<<<(HH * BB + 255) / 256, 256>>>();
    zero_hp_kernel<<<(BB * 1024 + 255) / 256, 256>>>();
    {
        size_t total = (size_t)2 * 1024 * DD;
        copy_wuwo_kernel<<<(unsigned)((total + 255) / 256), 256>>>(Wu, Wo);
    }
    enc16_kernel<<<(1024 * 1024 + 255) / 256, 256>>>(encf, enci);
    wqt_kernel<<<dim3(64, 32), dim3(32, 8)>>>(Wq);
    prep_mma_kernel<<<dim3(16, 4, 2), 256, XP_SMEM>>>();
    bias_enc_kernel<<<256, 256>>>(encf, enci, bq);
    bias_copy_kernel<<<9, 256>>>(bu, bo);
    wb_rows_kernel<<<dim3(8, 16), 256>>>(wfw, wiw);
    bias_wb_kernel<<<1, 512>>>(wfw, wiw);
    {
        size_t total = (size_t)NPAD * 2048;
        bsplit_kernel<<<(unsigned)((total + 255) / 256), 256>>>();
    }
    {
        size_t total = (size_t)T_STEPS * BB * 1024;
        xprep_kernel<<<(unsigned)((total + 255) / 256), 256>>>(X);
    }

    // ---- fused recurrence + xpre engine, ONE persistent kernel ----
    dim3 grid_step(33, 4);   // 132 CTAs, all resident
    persist_kernel<<<grid_step, 384, GSMEM>>>(out, wfw, wfb, wiw, wib);

    tail_kernel<<<(BB * HH + 255) / 256, 256>>>(out);
}

// round 15
// speedup vs baseline: 1.5597x; 1.5597x over previous
#include <cuda_runtime.h>
#include <cuda.h>
#include <cuda_fp16.h>
#include <math.h>
#include <stdint.h>

// Problem dims
#define T_STEPS 128
#define BB      256
#define DIN     1024
#define HH      1024
#define NQ      8
#define DD      2048
#define NC      4112          // zf|zi|g|o|basef(8)|basei(8)
#define NPAD    4224          // 33 tiles of 128
#define NCTA    132

// ---------------- persistent device scratch ----------------
__device__ float g_Wall[(size_t)NC * DD];
__device__ float g_ball[NPAD];
__device__ __align__(256) __half g_Bpx[(size_t)NPAD * 1024];        // Wx fp16
__device__ __align__(256) __half g_Bph[(size_t)NPAD * 1024];        // Wh fp16
__device__ __align__(256) __half g_Xp[(size_t)T_STEPS * BB * 1024]; // fp16(X)
__device__ __align__(256) __half g_Hp[(size_t)BB * 1024];           // fp16(hx)
__device__ __align__(256) __half g_encf16[1024 * 1024];
__device__ __align__(256) __half g_enci16[1024 * 1024];
__device__ __align__(256) __half g_WqT[2048 * 1024];                // Wq^T fp16 [d][q]
__device__ float g_CXall[(size_t)T_STEPS * NPAD * BB];              // X-part C^T per t (+bias)
__device__ float g_CTh[(size_t)NPAD * BB];                          // H-part C^T
__device__ float g_CXT[HH * BB];                                    // cell state [h][b]
__device__ unsigned long long g_bar = 0;                            // monotonic tickets

// ============================================================
// common mma helpers
// ============================================================
__device__ __forceinline__ uint32_t smem_u32(const void* p) {
    uint32_t a;
    asm("{ .reg .u64 t; cvta.to.shared.u64 t, %1; cvt.u32.u64 %0, t; }" : "=r"(a) : "l"(p));
    return a;
}
__device__ __forceinline__ void cp_async16(uint32_t dst, const void* src) {
    asm volatile("cp.async.cg.shared.global [%0], [%1], 16;" :: "r"(dst), "l"(src));
}
__device__ __forceinline__ void ldmatrix_x4(uint32_t& r0, uint32_t& r1,
                                            uint32_t& r2, uint32_t& r3, uint32_t a) {
    asm volatile("ldmatrix.sync.aligned.m8n8.x4.shared.b16 {%0,%1,%2,%3}, [%4];"
                 : "=r"(r0), "=r"(r1), "=r"(r2), "=r"(r3) : "r"(a));
}
__device__ __forceinline__ void mma_f16(float* c, const uint32_t* a,
                                        uint32_t b0, uint32_t b1) {
    asm volatile("mma.sync.aligned.m16n8k16.row.col.f32.f16.f16.f32 "
                 "{%0,%1,%2,%3}, {%4,%5,%6,%7}, {%8,%9}, {%0,%1,%2,%3};"
                 : "+f"(c[0]), "+f"(c[1]), "+f"(c[2]), "+f"(c[3])
                 : "r"(a[0]), "r"(a[1]), "r"(a[2]), "r"(a[3]), "r"(b0), "r"(b1));
}
__device__ __forceinline__ float sigf(float x) {
    float e = __expf(-x);
    return __fdividef(1.f, 1.f + e);
}

// ============================================================
// Loop H-GEMM: block 64(M)x128(N), 8 warps (2Mx4N), warp 32x32,
// K=1024, BK=32, 3-stage. (R11/R13-validated)
// ============================================================
#define APITCH  40
#define A_ST    (64 * APITCH * 2)        // 5120
#define B_ST    (128 * APITCH * 2)       // 10240
#define STG_B   (A_ST + B_ST)            // 15360
#define GSMEM   (3 * STG_B)              // 46080
#define NTL     32

#define GBAR_WARPS() asm volatile("bar.sync 1, 256;" ::: "memory")

__device__ __forceinline__ void gemm64(const __half* __restrict__ Asrc,
                                       const __half* __restrict__ Bsrc,
                                       float* __restrict__ Cdst,
                                       int m0, int n0, uint32_t sb, int tid)
{
    const int lane = tid & 31, wid = tid >> 5;
    const int wm = wid & 1, wn = wid >> 1;

    const int arow = tid >> 2, ach = tid & 3;
    const __half* gA = Asrc + (size_t)(m0 + arow) * 1024 + ach * 8;
    const uint32_t daB = sb + (arow * APITCH + ach * 8) * 2;
    const int brow = tid >> 1, bch = tid & 1;
    const __half* gB = Bsrc + (size_t)(n0 + brow) * 1024 + bch * 16;
    const uint32_t dbB = sb + A_ST + (brow * APITCH + bch * 16) * 2;

    float acc[2][4][4];
#pragma unroll
    for (int i = 0; i < 2; i++)
#pragma unroll
        for (int j = 0; j < 4; j++)
#pragma unroll
            for (int r = 0; r < 4; r++) acc[i][j][r] = 0.f;

    const uint32_t aA0 = sb + ((wm * 32 + (lane & 15)) * APITCH + (lane >> 4) * 8) * 2;
    const int brl = wn * 32 + (lane & 7) + ((lane >> 4) << 3);
    const uint32_t bA0 = sb + A_ST + (brl * APITCH + ((lane >> 3) & 1) * 8) * 2;

    auto issue = [&](int kt, int st) {
        cp_async16(daB + st * STG_B, gA + kt * 32);
        const uint32_t db = dbB + st * STG_B;
        const __half* gb = gB + kt * 32;
        cp_async16(db, gb);
        cp_async16(db + 16, gb + 8);
    };

#pragma unroll
    for (int s = 0; s < 2; s++) {
        issue(s, s);
        asm volatile("cp.async.commit_group;");
    }

    for (int kt = 0; kt < NTL; kt++) {
        asm volatile("cp.async.wait_group 1;");
        GBAR_WARPS();
        if (kt + 2 < NTL) issue(kt + 2, (kt + 2) % 3);
        asm volatile("cp.async.commit_group;");

        const int st = kt % 3;
        const uint32_t aB = aA0 + st * STG_B;
        const uint32_t bB = bA0 + st * STG_B;
#pragma unroll
        for (int kk = 0; kk < 2; kk++) {
            uint32_t a[2][4], b[2][4];
#pragma unroll
            for (int mf = 0; mf < 2; mf++)
                ldmatrix_x4(a[mf][0], a[mf][1], a[mf][2], a[mf][3],
                            aB + (mf * 16 * APITCH + kk * 16) * 2);
#pragma unroll
            for (int nf = 0; nf < 2; nf++)
                ldmatrix_x4(b[nf][0], b[nf][1], b[nf][2], b[nf][3],
                            bB + (nf * 16 * APITCH + kk * 16) * 2);
#pragma unroll
            for (int mf = 0; mf < 2; mf++)
#pragma unroll
                for (int nf = 0; nf < 2; nf++) {
                    mma_f16(acc[mf][nf * 2 + 0], a[mf], b[nf][0], b[nf][1]);
                    mma_f16(acc[mf][nf * 2 + 1], a[mf], b[nf][2], b[nf][3]);
                }
        }
    }

#pragma unroll
    for (int mf = 0; mf < 2; mf++) {
        const int mb = m0 + wm * 32 + mf * 16 + (lane >> 2);
#pragma unroll
        for (int j = 0; j < 4; j++) {
            const int nb = n0 + wn * 32 + j * 8 + 2 * (lane & 3);
            Cdst[(size_t)nb * BB + mb]           = acc[mf][j][0];
            Cdst[(size_t)(nb + 1) * BB + mb]     = acc[mf][j][1];
            Cdst[(size_t)nb * BB + mb + 8]       = acc[mf][j][2];
            Cdst[(size_t)(nb + 1) * BB + mb + 8] = acc[mf][j][3];
        }
    }
}

__device__ __forceinline__ void grid_bar(int tid) {
    __syncthreads();
    if (tid == 0) {
        __threadfence();
        unsigned long long t0 = atomicAdd(&g_bar, 1ULL);
        unsigned long long tgt = (t0 / (unsigned long long)NCTA + 1ULL) * (unsigned long long)NCTA;
        while (*((volatile unsigned long long*)&g_bar) < tgt) { }   // tight spin
        __threadfence();
    }
    __syncthreads();
}

// ============================================================
// Persistent loop kernel: H-GEMM + elem per step (R13 structure)
// ============================================================
__global__ __launch_bounds__(384, 1) void persist_kernel(
    float* __restrict__ out,
    const float* __restrict__ wfw, const float* __restrict__ wfb,
    const float* __restrict__ wiw, const float* __restrict__ wib)
{
    extern __shared__ __align__(16) char smraw[];
    const uint32_t sb = smem_u32(smraw);
    const int tid = threadIdx.x;
    const int n0 = blockIdx.x * 128, m0 = blockIdx.y * 64;
    const int cta = blockIdx.y * 33 + blockIdx.x;

    for (int t = 0; t < T_STEPS; t++) {
        if (tid < 256)
            gemm64(g_Hp, g_Bph, g_CTh, m0, n0, sb, tid);
        grid_bar(tid);

        const float* cth = g_CTh;
        const float* ctx = g_CXall + (size_t)t * NPAD * BB;
        float* out_t = out + (size_t)t * BB * HH;
        const bool last = (t == T_STEPS - 1);
#pragma unroll 1
        for (int k = 0; k < 6; k++) {
            int id = cta * 384 + tid + k * (NCTA * 384);
            if (id >= BB * HH) break;
            int h = id >> 8, b = id & 255;
            auto rd = [&](int n) {
                size_t p = (size_t)n * BB + b;
                return cth[p] + ctx[p];
            };
            float f_pre, i_pre;
            if (h < NQ) {
                float df[NQ], di[NQ];
                f_pre = 0.f; i_pre = 0.f;
#pragma unroll
                for (int i = 0; i < NQ; i++) {
                    float dot = rd(4096 + i) + __ldg(&wfb[i]);
#pragma unroll
                    for (int kk = 0; kk < NQ; kk++)
                        if (kk < i) dot += df[kk] * __ldg(&wfw[i * 1024 + kk]);
                    float v = tanhf(dot);
                    df[i] = v - rd(i);
                    if (i == h) f_pre = v;
                }
#pragma unroll
                for (int i = 0; i < NQ; i++) {
                    float dot = rd(4104 + i) + __ldg(&wib[i]);
#pragma unroll
                    for (int kk = 0; kk < NQ; kk++)
                        if (kk < i) dot += di[kk] * __ldg(&wiw[i * 1024 + kk]);
                    float v = tanhf(dot);
                    di[i] = v - rd(1024 + i);
                    if (i == h) i_pre = v;
                }
            } else {
                f_pre = rd(h);
                i_pre = rd(1024 + h);
            }
            const float gg = tanhf(rd(2048 + h));
            const float o  = sigf(rd(3072 + h));
            const size_t p = (size_t)h * BB + b;
            const float c = sigf(f_pre) * g_CXT[p] + sigf(i_pre) * gg;
            g_CXT[p] = c;
            const float hv = o * tanhf(c);
            out_t[(size_t)b * HH + h] = hv;
            g_Hp[(size_t)b * 1024 + h] = __float2half(hv);
            if (last) {
                // tail: out[T] = hx, out[T+1] = cx
                out[(size_t)T_STEPS * BB * HH + (size_t)b * HH + h] = hv;
                out[(size_t)T_STEPS * BB * HH + (size_t)BB * HH + (size_t)b * HH + h] = c;
            }
        }
        grid_bar(tid);
    }
}

// ============================================================
// Big-GEMM core: block 256(M)x128(N), 8 warps (4Mx2N), warp 64x64,
// K=1024, BK=32, 4-stage. (R8/R13-validated geometry)
// ============================================================
#define XAP     40
#define XP_AST  (256 * XAP * 2)          // 20480
#define XP_BST  (128 * XAP * 2)          // 10240
#define XP_STG  (XP_AST + XP_BST)        // 30720
#define XP_SMEM (4 * XP_STG)             // 122880

struct Acc256 { float v[4][8][4]; };

__device__ __forceinline__ void big_mainloop(const __half* __restrict__ Asrc,
                                             const __half* __restrict__ Bsrc,
                                             int m0, int n0, uint32_t sb, int tid,
                                             Acc256& A)
{
    const int lane = tid & 31, wid = tid >> 5;
    const int wm = wid >> 1, wn = wid & 1;

    const __half* gA = Asrc + (size_t)(m0 + tid) * 1024;     // 1 thread/row, 64B
    const uint32_t daB = sb + (tid * XAP) * 2;
    const int brow = tid >> 1, bch = tid & 1;
    const __half* gB = Bsrc + (size_t)(n0 + brow) * 1024 + bch * 16;
    const uint32_t dbB = sb + XP_AST + (brow * XAP + bch * 16) * 2;

    auto issue = [&](int kt, int st) {
        const uint32_t da = daB + st * XP_STG;
        const __half* ga = gA + kt * 32;
#pragma unroll
        for (int j = 0; j < 4; j++) cp_async16(da + j * 16, ga + j * 8);
        const uint32_t db = dbB + st * XP_STG;
        const __half* gb = gB + kt * 32;
        cp_async16(db, gb);
        cp_async16(db + 16, gb + 8);
    };

#pragma unroll
    for (int i = 0; i < 4; i++)
#pragma unroll
        for (int j = 0; j < 8; j++)
#pragma unroll
            for (int r = 0; r < 4; r++) A.v[i][j][r] = 0.f;

    const uint32_t aA0 = sb + ((wm * 64 + (lane & 15)) * XAP + (lane >> 4) * 8) * 2;
    const int brl = wn * 64 + (lane & 7) + ((lane >> 4) << 3);
    const uint32_t bA0 = sb + XP_AST + (brl * XAP + ((lane >> 3) & 1) * 8) * 2;

#pragma unroll
    for (int s = 0; s < 3; s++) {
        issue(s, s);
        asm volatile("cp.async.commit_group;");
    }

    for (int kt = 0; kt < 32; kt++) {
        asm volatile("cp.async.wait_group 2;");
        __syncthreads();
        if (kt + 3 < 32) issue(kt + 3, (kt + 3) & 3);
        asm volatile("cp.async.commit_group;");

        const int st = kt & 3;
        const uint32_t aB = aA0 + st * XP_STG;
        const uint32_t bB = bA0 + st * XP_STG;
#pragma unroll
        for (int kk = 0; kk < 2; kk++) {
            uint32_t a[4][4], b[4][4];
#pragma unroll
            for (int mf = 0; mf < 4; mf++)
                ldmatrix_x4(a[mf][0], a[mf][1], a[mf][2], a[mf][3],
                            aB + (mf * 16 * XAP + kk * 16) * 2);
#pragma unroll
            for (int nf = 0; nf < 4; nf++)
                ldmatrix_x4(b[nf][0], b[nf][1], b[nf][2], b[nf][3],
                            bB + (nf * 16 * XAP + kk * 16) * 2);
#pragma unroll
            for (int mf = 0; mf < 4; mf++)
#pragma unroll
                for (int nf = 0; nf < 4; nf++) {
                    mma_f16(A.v[mf][nf * 2 + 0], a[mf], b[nf][0], b[nf][1]);
                    mma_f16(A.v[mf][nf * 2 + 1], a[mf], b[nf][2], b[nf][3]);
                }
        }
    }
}

// X precompute: CXall[t][n][b] = X[t]@Wx^T + bias.  grid (33, 128)
__global__ __launch_bounds__(256, 1) void xpre_kernel()
{
    extern __shared__ __align__(16) char smraw[];
    const uint32_t sb = smem_u32(smraw);
    const int tid = threadIdx.x, lane = tid & 31, wid = tid >> 5;
    const int wm = wid >> 1, wn = wid & 1;
    const int n0 = blockIdx.x * 128;
    const int m0 = blockIdx.y * 256;         // blockIdx.y = t

    Acc256 A;
    big_mainloop(g_Xp, g_Bpx, m0, n0, sb, tid, A);

    float* ct = g_CXall + (size_t)blockIdx.y * NPAD * BB;
#pragma unroll
    for (int mf = 0; mf < 4; mf++) {
        const int mb = wm * 64 + mf * 16 + (lane >> 2);   // = batch b
#pragma unroll
        for (int q = 0; q < 8; q++) {
            const int nb = n0 + wn * 64 + q * 8 + 2 * (lane & 3);
            const float b0 = __ldg(&g_ball[nb]), b1 = __ldg(&g_ball[nb + 1]);
            ct[(size_t)nb * BB + mb]           = A.v[mf][q][0] + b0;
            ct[(size_t)(nb + 1) * BB + mb]     = A.v[mf][q][1] + b1;
            ct[(size_t)nb * BB + mb + 8]       = A.v[mf][q][2] + b0;
            ct[(size_t)(nb + 1) * BB + mb + 8] = A.v[mf][q][3] + b1;
        }
    }
}

// prep: Wall rows [z*1024 .. +1024) = enc_z @ Wq.  grid (16, 4, 2)
__global__ __launch_bounds__(256, 1) void prep_mma_kernel()
{
    extern __shared__ __align__(16) char smraw[];
    const uint32_t sb = smem_u32(smraw);
    const int tid = threadIdx.x, lane = tid & 31, wid = tid >> 5;
    const int wm = wid >> 1, wn = wid & 1;
    const int n0 = blockIdx.x * 128;
    const int m0 = blockIdx.y * 256;
    const int z  = blockIdx.z;

    Acc256 A;
    big_mainloop(z ? g_enci16 : g_encf16, g_WqT, m0, n0, sb, tid, A);

    float* Wdst = g_Wall + (size_t)(z * 1024 + m0) * DD;
#pragma unroll
    for (int mf = 0; mf < 4; mf++) {
        const int mb = wm * 64 + mf * 16 + (lane >> 2);
#pragma unroll
        for (int q = 0; q < 8; q++) {
            const int nb = n0 + wn * 64 + q * 8 + 2 * (lane & 3);
            Wdst[(size_t)mb * DD + nb]           = A.v[mf][q][0];
            Wdst[(size_t)mb * DD + nb + 1]       = A.v[mf][q][1];
            Wdst[(size_t)(mb + 8) * DD + nb]     = A.v[mf][q][2];
            Wdst[(size_t)(mb + 8) * DD + nb + 1] = A.v[mf][q][3];
        }
    }
}

// ============================================================
// small prep kernels
// ============================================================
__global__ void init_state_kernel() {
    int idx = blockIdx.x * blockDim.x + threadIdx.x;
    if (idx < HH * BB) {
        g_CXT[idx] = 0.f;
        g_Hp[idx] = __float2half(0.f);
    }
}
__global__ void copy_wuwo_kernel(const float* __restrict__ Wu, const float* __restrict__ Wo) {
    size_t idx = (size_t)blockIdx.x * blockDim.x + threadIdx.x;
    size_t total = (size_t)2 * 1024 * DD;
    if (idx < total) {
        float v = (idx < (size_t)1024 * DD) ? Wu[idx] : Wo[idx - (size_t)1024 * DD];
        g_Wall[(size_t)2048 * DD + idx] = v;
    }
}
__global__ void enc16_kernel(const float* __restrict__ encf, const float* __restrict__ enci) {
    int idx = blockIdx.x * blockDim.x + threadIdx.x;
    if (idx < 1024 * 1024) {
        g_encf16[idx] = __float2half(encf[idx]);
        g_enci16[idx] = __float2half(enci[idx]);
    }
}
__global__ void wqt_kernel(const float* __restrict__ Wq) {
    __shared__ float tile[32][33];
    int dx = blockIdx.x * 32, qy = blockIdx.y * 32;
    int tx = threadIdx.x, ty = threadIdx.y;
#pragma unroll
    for (int r = 0; r < 4; r++)
        tile[ty + r * 8][tx] = Wq[(size_t)(qy + ty + r * 8) * 2048 + dx + tx];
    __syncthreads();
#pragma unroll
    for (int r = 0; r < 4; r++)
        g_WqT[(size_t)(dx + ty + r * 8) * 1024 + qy + tx] =
            __float2half(tile[tx][ty + r * 8]);
}
__global__ void bias_enc_kernel(const float* __restrict__ encf, const float* __restrict__ enci,
                                const float* __restrict__ bq)
{
    int w = (blockIdx.x * blockDim.x + threadIdx.x) >> 5;
    int lane = threadIdx.x & 31;
    if (w >= 2048) return;
    const float* enc = (w < 1024) ? encf : enci;
    int row = w & 1023;
    float s = 0.f;
    for (int j = lane; j < 1024; j += 32) s += enc[row * 1024 + j] * bq[j];
#pragma unroll
    for (int o = 16; o > 0; o >>= 1) s += __shfl_xor_sync(0xFFFFFFFF, s, o);
    if (lane == 0) g_ball[w] = s;
}
__global__ void bias_copy_kernel(const float* __restrict__ bu, const float* __restrict__ bo) {
    int n = 2048 + blockIdx.x * blockDim.x + threadIdx.x;
    if (n < 3072) g_ball[n] = bu[n - 2048];
    else if (n < 4096) g_ball[n] = bo[n - 3072];
    else if (n >= 4112 && n < NPAD) g_ball[n] = 0.f;
}
__global__ void wb_rows_kernel(const float* __restrict__ wfw, const float* __restrict__ wiw) {
    int i16 = blockIdx.y;
    int d = blockIdx.x * 256 + threadIdx.x;
    int g = i16 >> 3, i = i16 & 7;
    const float* ww = g ? wiw : wfw;
    float s = 0.f;
    for (int j = 0; j < 1024; j++)
        s += __ldg(&ww[i * 1024 + j]) * g_Wall[(size_t)(g * 1024 + j) * DD + d];
    g_Wall[(size_t)(4096 + i16) * DD + d] = s;
}
__global__ void bias_wb_kernel(const float* __restrict__ wfw, const float* __restrict__ wiw) {
    int w = threadIdx.x >> 5, lane = threadIdx.x & 31;
    if (w >= 16) return;
    int g = w >> 3, i = w & 7;
    const float* ww = g ? wiw : wfw;
    const float* bb = g_ball + g * 1024;
    float s = 0.f;
    for (int j = lane; j < 1024; j += 32) s += ww[i * 1024 + j] * bb[j];
#pragma unroll
    for (int o = 16; o > 0; o >>= 1) s += __shfl_xor_sync(0xFFFFFFFF, s, o);
    if (lane == 0) g_ball[4096 + w] = s;
}
__global__ void bsplit_kernel() {
    size_t idx = (size_t)blockIdx.x * blockDim.x + threadIdx.x;
    if (idx >= (size_t)NPAD * 2048) return;
    int n = (int)(idx / 2048), c = (int)(idx % 2048);
    float v = (n < NC) ? g_Wall[(size_t)n * DD + c] : 0.f;
    if (c < 1024) g_Bpx[(size_t)n * 1024 + c] = __float2half(v);
    else          g_Bph[(size_t)n * 1024 + (c - 1024)] = __float2half(v);
}
__global__ void xprep_kernel(const float* __restrict__ X) {
    size_t idx = (size_t)blockIdx.x * blockDim.x + threadIdx.x;
    if (idx < (size_t)T_STEPS * BB * 1024)
        g_Xp[idx] = __float2half(X[idx]);
}

// ============================================================
// host
// ============================================================
extern "C" void kernel_launch(void* const* d_in, const int* in_sizes, int n_in,
                              void* d_out, int out_size)
{
    const float* X    = (const float*)d_in[0];
    const float* Wq   = (const float*)d_in[1];
    const float* bq   = (const float*)d_in[2];
    const float* encf = (const float*)d_in[3];
    const float* wfw  = (const float*)d_in[4];
    const float* wfb  = (const float*)d_in[5];
    const float* enci = (const float*)d_in[6];
    const float* wiw  = (const float*)d_in[7];
    const float* wib  = (const float*)d_in[8];
    const float* Wu   = (const float*)d_in[9];
    const float* bu   = (const float*)d_in[10];
    const float* Wo   = (const float*)d_in[11];
    const float* bo   = (const float*)d_in[12];
    float* out = (float*)d_out;

    static bool attr_done = false;
    if (!attr_done) {
        cudaFuncSetAttribute(persist_kernel, cudaFuncAttributeMaxDynamicSharedMemorySize, GSMEM);
        cudaFuncSetAttribute(xpre_kernel, cudaFuncAttributeMaxDynamicSharedMemorySize, XP_SMEM);
        cudaFuncSetAttribute(prep_mma_kernel, cudaFuncAttributeMaxDynamicSharedMemorySize, XP_SMEM);
        attr_done = true;
    }

    // ---- prep ----
    init_state_kernel<<<(HH * BB + 255) / 256, 256>>>();
    {
        size_t total = (size_t)2 * 1024 * DD;
        copy_wuwo_kernel<<<(unsigned)((total + 255) / 256), 256>>>(Wu, Wo);
    }
    enc16_kernel<<<(1024 * 1024 + 255) / 256, 256>>>(encf, enci);
    wqt_kernel<<<dim3(64, 32), dim3(32, 8)>>>(Wq);
    prep_mma_kernel<<<dim3(16, 4, 2), 256, XP_SMEM>>>();
    bias_enc_kernel<<<256, 256>>>(encf, enci, bq);
    bias_copy_kernel<<<9, 256>>>(bu, bo);
    wb_rows_kernel<<<dim3(8, 16), 256>>>(wfw, wiw);
    bias_wb_kernel<<<1, 512>>>(wfw, wiw);
    {
        size_t total = (size_t)NPAD * 2048;
        bsplit_kernel<<<(unsigned)((total + 255) / 256), 256>>>();
    }
    {
        size_t total = (size_t)T_STEPS * BB * 1024;
        xprep_kernel<<<(unsigned)((total + 255) / 256), 256>>>(X);
    }

    // ---- X precompute: one big GEMM for all timesteps ----
    xpre_kernel<<<dim3(33, T_STEPS), 256, XP_SMEM>>>();

    // ---- recurrence: persistent H-GEMM + elem (tail fused into last step) ----
    dim3 grid_step(33, 4);   // 132 CTAs, all resident
    persist_kernel<<<grid_step, 384, GSMEM>>>(out, wfw, wfb, wiw, wib);
}

// round 16
// speedup vs baseline: 1.6924x; 1.0851x over previous
#include <cuda_runtime.h>
#include <cuda.h>
#include <cuda_fp16.h>
#include <math.h>
#include <stdint.h>

// Problem dims
#define T_STEPS 128
#define BB      256
#define DIN     1024
#define HH      1024
#define NQ      8
#define DD      2048
#define NC      4112          // 4096 gates + 16 base
#define NPAD    4224          // 33 tiles of 128
#define NCTA    132

// Column permutation: n' in [0,16) = base (orig 4096+n'); n' in [16,4112):
// g=(n'-16)&3, h=(n'-16)>>2, orig = g*1024+h; n' >= 4112: zero pad.

// ---------------- persistent device scratch ----------------
__device__ float g_Wall[(size_t)NC * DD];
__device__ float g_ball[NPAD];                                      // orig order
__device__ float g_ballp[NPAD];                                     // permuted
__device__ __align__(256) __half g_Bpx[(size_t)NPAD * 1024];        // Wx fp16 (permuted rows)
__device__ __align__(256) __half g_Bph[(size_t)NPAD * 1024];        // Wh fp16 (permuted rows)
__device__ __align__(256) __half g_Xp[(size_t)T_STEPS * BB * 1024]; // fp16(X)
__device__ __align__(256) __half g_Hp[(size_t)BB * 1024];           // fp16(hx)
__device__ __align__(256) __half g_encf16[1024 * 1024];
__device__ __align__(256) __half g_enci16[1024 * 1024];
__device__ __align__(256) __half g_WqT[2048 * 1024];                // Wq^T fp16 [d][q]
__device__ float g_CXall[(size_t)T_STEPS * NPAD * BB];              // X-part C^T per t (+bias, permuted)
__device__ float g_CXT[HH * BB];                                    // cell state [h][b]
__device__ unsigned long long g_bar = 0;                            // monotonic tickets

// ============================================================
// common mma helpers
// ============================================================
__device__ __forceinline__ uint32_t smem_u32(const void* p) {
    uint32_t a;
    asm("{ .reg .u64 t; cvta.to.shared.u64 t, %1; cvt.u32.u64 %0, t; }" : "=r"(a) : "l"(p));
    return a;
}
__device__ __forceinline__ void cp_async16(uint32_t dst, const void* src) {
    asm volatile("cp.async.cg.shared.global [%0], [%1], 16;" :: "r"(dst), "l"(src));
}
__device__ __forceinline__ void ldmatrix_x4(uint32_t& r0, uint32_t& r1,
                                            uint32_t& r2, uint32_t& r3, uint32_t a) {
    asm volatile("ldmatrix.sync.aligned.m8n8.x4.shared.b16 {%0,%1,%2,%3}, [%4];"
                 : "=r"(r0), "=r"(r1), "=r"(r2), "=r"(r3) : "r"(a));
}
__device__ __forceinline__ void mma_f16(float* c, const uint32_t* a,
                                        uint32_t b0, uint32_t b1) {
    asm volatile("mma.sync.aligned.m16n8k16.row.col.f32.f16.f16.f32 "
                 "{%0,%1,%2,%3}, {%4,%5,%6,%7}, {%8,%9}, {%0,%1,%2,%3};"
                 : "+f"(c[0]), "+f"(c[1]), "+f"(c[2]), "+f"(c[3])
                 : "r"(a[0]), "r"(a[1]), "r"(a[2]), "r"(a[3]), "r"(b0), "r"(b1));
}
__device__ __forceinline__ float sigf(float x) {
    float e = __expf(-x);
    return __fdividef(1.f, 1.f + e);
}

// ============================================================
// Loop H-GEMM: block 64(M)x128(N), 8 warps (2Mx4N), warp 32x32,
// K=1024, BK=32, 3-stage -> accumulators stored to SMEM C tile.
// ============================================================
#define APITCH  40
#define A_ST    (64 * APITCH * 2)        // 5120
#define B_ST    (128 * APITCH * 2)       // 10240
#define STG_B   (A_ST + B_ST)            // 15360
#define PIPE_TOT (3 * STG_B)             // 46080
#define CSM_PITCH 65
#define CSM_B   (128 * CSM_PITCH * 4)    // 33280
#define GSMEM   (PIPE_TOT + CSM_B)       // 79360
#define NTL     32

#define GBAR_WARPS() asm volatile("bar.sync 1, 256;" ::: "memory")

__device__ __forceinline__ void gemm64s(const __half* __restrict__ Asrc,
                                        const __half* __restrict__ Bsrc,
                                        float* __restrict__ Csm,
                                        int m0, int n0, uint32_t sb, int tid)
{
    const int lane = tid & 31, wid = tid >> 5;
    const int wm = wid & 1, wn = wid >> 1;

    const int arow = tid >> 2, ach = tid & 3;
    const __half* gA = Asrc + (size_t)(m0 + arow) * 1024 + ach * 8;
    const uint32_t daB = sb + (arow * APITCH + ach * 8) * 2;
    const int brow = tid >> 1, bch = tid & 1;
    const __half* gB = Bsrc + (size_t)(n0 + brow) * 1024 + bch * 16;
    const uint32_t dbB = sb + A_ST + (brow * APITCH + bch * 16) * 2;

    float acc[2][4][4];
#pragma unroll
    for (int i = 0; i < 2; i++)
#pragma unroll
        for (int j = 0; j < 4; j++)
#pragma unroll
            for (int r = 0; r < 4; r++) acc[i][j][r] = 0.f;

    const uint32_t aA0 = sb + ((wm * 32 + (lane & 15)) * APITCH + (lane >> 4) * 8) * 2;
    const int brl = wn * 32 + (lane & 7) + ((lane >> 4) << 3);
    const uint32_t bA0 = sb + A_ST + (brl * APITCH + ((lane >> 3) & 1) * 8) * 2;

    auto issue = [&](int kt, int st) {
        cp_async16(daB + st * STG_B, gA + kt * 32);
        const uint32_t db = dbB + st * STG_B;
        const __half* gb = gB + kt * 32;
        cp_async16(db, gb);
        cp_async16(db + 16, gb + 8);
    };

#pragma unroll
    for (int s = 0; s < 2; s++) {
        issue(s, s);
        asm volatile("cp.async.commit_group;");
    }

    for (int kt = 0; kt < NTL; kt++) {
        asm volatile("cp.async.wait_group 1;");
        GBAR_WARPS();
        if (kt + 2 < NTL) issue(kt + 2, (kt + 2) % 3);
        asm volatile("cp.async.commit_group;");

        const int st = kt % 3;
        const uint32_t aB = aA0 + st * STG_B;
        const uint32_t bB = bA0 + st * STG_B;
#pragma unroll
        for (int kk = 0; kk < 2; kk++) {
            uint32_t a[2][4], b[2][4];
#pragma unroll
            for (int mf = 0; mf < 2; mf++)
                ldmatrix_x4(a[mf][0], a[mf][1], a[mf][2], a[mf][3],
                            aB + (mf * 16 * APITCH + kk * 16) * 2);
#pragma unroll
            for (int nf = 0; nf < 2; nf++)
                ldmatrix_x4(b[nf][0], b[nf][1], b[nf][2], b[nf][3],
                            bB + (nf * 16 * APITCH + kk * 16) * 2);
#pragma unroll
            for (int mf = 0; mf < 2; mf++)
#pragma unroll
                for (int nf = 0; nf < 2; nf++) {
                    mma_f16(acc[mf][nf * 2 + 0], a[mf], b[nf][0], b[nf][1]);
                    mma_f16(acc[mf][nf * 2 + 1], a[mf], b[nf][2], b[nf][3]);
                }
        }
    }

    // epilogue: accumulators -> CTA-local smem tile Csm[n_local][m_local]
#pragma unroll
    for (int mf = 0; mf < 2; mf++) {
        const int ml = wm * 32 + mf * 16 + (lane >> 2);
#pragma unroll
        for (int j = 0; j < 4; j++) {
            const int nl = wn * 32 + j * 8 + 2 * (lane & 3);
            Csm[nl * CSM_PITCH + ml]           = acc[mf][j][0];
            Csm[(nl + 1) * CSM_PITCH + ml]     = acc[mf][j][1];
            Csm[nl * CSM_PITCH + ml + 8]       = acc[mf][j][2];
            Csm[(nl + 1) * CSM_PITCH + ml + 8] = acc[mf][j][3];
        }
    }
}

__device__ __forceinline__ void grid_bar(int tid) {
    __syncthreads();
    if (tid == 0) {
        __threadfence();
        unsigned long long t0 = atomicAdd(&g_bar, 1ULL);
        unsigned long long tgt = (t0 / (unsigned long long)NCTA + 1ULL) * (unsigned long long)NCTA;
        while (*((volatile unsigned long long*)&g_bar) < tgt) { }
        __threadfence();
    }
    __syncthreads();
}

// ============================================================
// Persistent loop kernel: H-GEMM(smem C) + local elem, ONE bar/step
// ============================================================
__global__ __launch_bounds__(384, 1) void persist_kernel(
    float* __restrict__ out,
    const float* __restrict__ wfw, const float* __restrict__ wfb,
    const float* __restrict__ wiw, const float* __restrict__ wib)
{
    extern __shared__ __align__(16) char smraw[];
    const uint32_t sb = smem_u32(smraw);
    float* Csm = (float*)(smraw + PIPE_TOT);
    const int tid = threadIdx.x;
    const int nx = blockIdx.x, my = blockIdx.y;
    const int n0 = nx * 128, m0 = my * 64;

    // h range owned by this N-tile (gate-interleaved layout)
    const int h0   = (nx == 0) ? 0 : (32 * nx - 4);
    const int hcnt = (nx == 0) ? 28 : ((nx == 32) ? 4 : 32);
    const int loff = (nx == 0) ? 16 : 0;

    for (int t = 0; t < T_STEPS; t++) {
        if (tid < 256)
            gemm64s(g_Hp, g_Bph, Csm, m0, n0, sb, tid);
        __syncthreads();   // Csm visible to all 384 threads

        const float* ctx = g_CXall + (size_t)t * NPAD * BB;
        float* out_t = out + (size_t)t * BB * HH;
        const bool last = (t == T_STEPS - 1);
        const int total = hcnt * 64;
#pragma unroll 1
        for (int it = 0; it < 6; it++) {
            const int id = it * 384 + tid;
            if (id >= total) break;
            const int hi = id >> 6, bl = id & 63;
            const int h = h0 + hi, b = m0 + bl;
            auto rdl = [&](int nl) {
                return Csm[nl * CSM_PITCH + bl] +
                       ctx[(size_t)(n0 + nl) * BB + b];
            };
            float f_pre, i_pre;
            if (h < NQ) {                      // only nx==0 CTAs
                float df[NQ], di[NQ];
                f_pre = 0.f; i_pre = 0.f;
#pragma unroll
                for (int i = 0; i < NQ; i++) {
                    float dot = rdl(i) + __ldg(&wfb[i]);     // base_f i
#pragma unroll
                    for (int kk = 0; kk < NQ; kk++)
                        if (kk < i) dot += df[kk] * __ldg(&wfw[i * 1024 + kk]);
                    float v = tanhf(dot);
                    df[i] = v - rdl(16 + 4 * i);             // zf_i pre
                    if (i == h) f_pre = v;
                }
#pragma unroll
                for (int i = 0; i < NQ; i++) {
                    float dot = rdl(8 + i) + __ldg(&wib[i]); // base_i i
#pragma unroll
                    for (int kk = 0; kk < NQ; kk++)
                        if (kk < i) dot += di[kk] * __ldg(&wiw[i * 1024 + kk]);
                    float v = tanhf(dot);
                    di[i] = v - rdl(16 + 4 * i + 1);         // zi_i pre
                    if (i == h) i_pre = v;
                }
            } else {
                f_pre = rdl(loff + 4 * hi);
                i_pre = rdl(loff + 4 * hi + 1);
            }
            const float gg = tanhf(rdl(loff + 4 * hi + 2));
            const float o  = sigf(rdl(loff + 4 * hi + 3));
            const size_t p = (size_t)h * BB + b;
            const float c = sigf(f_pre) * g_CXT[p] + sigf(i_pre) * gg;
            g_CXT[p] = c;
            const float hv = o * tanhf(c);
            out_t[(size_t)b * HH + h] = hv;
            g_Hp[(size_t)b * 1024 + h] = __float2half(hv);
            if (last) {
                out[(size_t)T_STEPS * BB * HH + (size_t)b * HH + h] = hv;
                out[(size_t)T_STEPS * BB * HH + (size_t)BB * HH + (size_t)b * HH + h] = c;
            }
        }
        grid_bar(tid);     // h-broadcast for step t+1
    }
}

// ============================================================
// Big-GEMM core: block 256(M)x128(N), 8 warps (4Mx2N), warp 64x64,
// K=1024, BK=32, 4-stage. (R8/R13-validated geometry)
// ============================================================
#define XAP     40
#define XP_AST  (256 * XAP * 2)          // 20480
#define XP_BST  (128 * XAP * 2)          // 10240
#define XP_STG  (XP_AST + XP_BST)        // 30720
#define XP_SMEM (4 * XP_STG)             // 122880

struct Acc256 { float v[4][8][4]; };

__device__ __forceinline__ void big_mainloop(const __half* __restrict__ Asrc,
                                             const __half* __restrict__ Bsrc,
                                             int m0, int n0, uint32_t sb, int tid,
                                             Acc256& A)
{
    const int lane = tid & 31, wid = tid >> 5;
    const int wm = wid >> 1, wn = wid & 1;

    const __half* gA = Asrc + (size_t)(m0 + tid) * 1024;
    const uint32_t daB = sb + (tid * XAP) * 2;
    const int brow = tid >> 1, bch = tid & 1;
    const __half* gB = Bsrc + (size_t)(n0 + brow) * 1024 + bch * 16;
    const uint32_t dbB = sb + XP_AST + (brow * XAP + bch * 16) * 2;

    auto issue = [&](int kt, int st) {
        const uint32_t da = daB + st * XP_STG;
        const __half* ga = gA + kt * 32;
#pragma unroll
        for (int j = 0; j < 4; j++) cp_async16(da + j * 16, ga + j * 8);
        const uint32_t db = dbB + st * XP_STG;
        const __half* gb = gB + kt * 32;
        cp_async16(db, gb);
        cp_async16(db + 16, gb + 8);
    };

#pragma unroll
    for (int i = 0; i < 4; i++)
#pragma unroll
        for (int j = 0; j < 8; j++)
#pragma unroll
            for (int r = 0; r < 4; r++) A.v[i][j][r] = 0.f;

    const uint32_t aA0 = sb + ((wm * 64 + (lane & 15)) * XAP + (lane >> 4) * 8) * 2;
    const int brl = wn * 64 + (lane & 7) + ((lane >> 4) << 3);
    const uint32_t bA0 = sb + XP_AST + (brl * XAP + ((lane >> 3) & 1) * 8) * 2;

#pragma unroll
    for (int s = 0; s < 3; s++) {
        issue(s, s);
        asm volatile("cp.async.commit_group;");
    }

    for (int kt = 0; kt < 32; kt++) {
        asm volatile("cp.async.wait_group 2;");
        __syncthreads();
        if (kt + 3 < 32) issue(kt + 3, (kt + 3) & 3);
        asm volatile("cp.async.commit_group;");

        const int st = kt & 3;
        const uint32_t aB = aA0 + st * XP_STG;
        const uint32_t bB = bA0 + st * XP_STG;
#pragma unroll
        for (int kk = 0; kk < 2; kk++) {
            uint32_t a[4][4], b[4][4];
#pragma unroll
            for (int mf = 0; mf < 4; mf++)
                ldmatrix_x4(a[mf][0], a[mf][1], a[mf][2], a[mf][3],
                            aB + (mf * 16 * XAP + kk * 16) * 2);
#pragma unroll
            for (int nf = 0; nf < 4; nf++)
                ldmatrix_x4(b[nf][0], b[nf][1], b[nf][2], b[nf][3],
                            bB + (nf * 16 * XAP + kk * 16) * 2);
#pragma unroll
            for (int mf = 0; mf < 4; mf++)
#pragma unroll
                for (int nf = 0; nf < 4; nf++) {
                    mma_f16(A.v[mf][nf * 2 + 0], a[mf], b[nf][0], b[nf][1]);
                    mma_f16(A.v[mf][nf * 2 + 1], a[mf], b[nf][2], b[nf][3]);
                }
        }
    }
}

// X precompute: CXall[t][n'][b] = X[t]@Wx^T + bias (permuted cols). grid (33, 128)
__global__ __launch_bounds__(256, 1) void xpre_kernel()
{
    extern __shared__ __align__(16) char smraw[];
    const uint32_t sb = smem_u32(smraw);
    const int tid = threadIdx.x, lane = tid & 31, wid = tid >> 5;
    const int wm = wid >> 1, wn = wid & 1;
    const int n0 = blockIdx.x * 128;
    const int m0 = blockIdx.y * 256;         // blockIdx.y = t

    Acc256 A;
    big_mainloop(g_Xp, g_Bpx, m0, n0, sb, tid, A);

    float* ct = g_CXall + (size_t)blockIdx.y * NPAD * BB;
#pragma unroll
    for (int mf = 0; mf < 4; mf++) {
        const int mb = wm * 64 + mf * 16 + (lane >> 2);
#pragma unroll
        for (int q = 0; q < 8; q++) {
            const int nb = n0 + wn * 64 + q * 8 + 2 * (lane & 3);
            const float b0 = __ldg(&g_ballp[nb]), b1 = __ldg(&g_ballp[nb + 1]);
            ct[(size_t)nb * BB + mb]           = A.v[mf][q][0] + b0;
            ct[(size_t)(nb + 1) * BB + mb]     = A.v[mf][q][1] + b1;
            ct[(size_t)nb * BB + mb + 8]       = A.v[mf][q][2] + b0;
            ct[(size_t)(nb + 1) * BB + mb + 8] = A.v[mf][q][3] + b1;
        }
    }
}

// prep: Wall rows [z*1024 .. +1024) = enc_z @ Wq.  grid (16, 4, 2)
__global__ __launch_bounds__(256, 1) void prep_mma_kernel()
{
    extern __shared__ __align__(16) char smraw[];
    const uint32_t sb = smem_u32(smraw);
    const int tid = threadIdx.x, lane = tid & 31, wid = tid >> 5;
    const int wm = wid >> 1, wn = wid & 1;
    const int n0 = blockIdx.x * 128;
    const int m0 = blockIdx.y * 256;
    const int z  = blockIdx.z;

    Acc256 A;
    big_mainloop(z ? g_enci16 : g_encf16, g_WqT, m0, n0, sb, tid, A);

    float* Wdst = g_Wall + (size_t)(z * 1024 + m0) * DD;
#pragma unroll
    for (int mf = 0; mf < 4; mf++) {
        const int mb = wm * 64 + mf * 16 + (lane >> 2);
#pragma unroll
        for (int q = 0; q < 8; q++) {
            const int nb = n0 + wn * 64 + q * 8 + 2 * (lane & 3);
            Wdst[(size_t)mb * DD + nb]           = A.v[mf][q][0];
            Wdst[(size_t)mb * DD + nb + 1]       = A.v[mf][q][1];
            Wdst[(size_t)(mb + 8) * DD + nb]     = A.v[mf][q][2];
            Wdst[(size_t)(mb + 8) * DD + nb + 1] = A.v[mf][q][3];
        }
    }
}

// ============================================================
// small prep kernels
// ============================================================
__global__ void init_state_kernel() {
    int idx = blockIdx.x * blockDim.x + threadIdx.x;
    if (idx < HH * BB) {
        g_CXT[idx] = 0.f;
        g_Hp[idx] = __float2half(0.f);
    }
}
__global__ void copy_wuwo_kernel(const float* __restrict__ Wu, const float* __restrict__ Wo) {
    size_t idx = (size_t)blockIdx.x * blockDim.x + threadIdx.x;
    size_t total = (size_t)2 * 1024 * DD;
    if (idx < total) {
        float v = (idx < (size_t)1024 * DD) ? Wu[idx] : Wo[idx - (size_t)1024 * DD];
        g_Wall[(size_t)2048 * DD + idx] = v;
    }
}
__global__ void enc16_kernel(const float* __restrict__ encf, const float* __restrict__ enci) {
    int idx = blockIdx.x * blockDim.x + threadIdx.x;
    if (idx < 1024 * 1024) {
        g_encf16[idx] = __float2half(encf[idx]);
        g_enci16[idx] = __float2half(enci[idx]);
    }
}
__global__ void wqt_kernel(const float* __restrict__ Wq) {
    __shared__ float tile[32][33];
    int dx = blockIdx.x * 32, qy = blockIdx.y * 32;
    int tx = threadIdx.x, ty = threadIdx.y;
#pragma unroll
    for (int r = 0; r < 4; r++)
        tile[ty + r * 8][tx] = Wq[(size_t)(qy + ty + r * 8) * 2048 + dx + tx];
    __syncthreads();
#pragma unroll
    for (int r = 0; r < 4; r++)
        g_WqT[(size_t)(dx + ty + r * 8) * 1024 + qy + tx] =
            __float2half(tile[tx][ty + r * 8]);
}
__global__ void bias_enc_kernel(const float* __restrict__ encf, const float* __restrict__ enci,
                                const float* __restrict__ bq)
{
    int w = (blockIdx.x * blockDim.x + threadIdx.x) >> 5;
    int lane = threadIdx.x & 31;
    if (w >= 2048) return;
    const float* enc = (w < 1024) ? encf : enci;
    int row = w & 1023;
    float s = 0.f;
    for (int j = lane; j < 1024; j += 32) s += enc[row * 1024 + j] * bq[j];
#pragma unroll
    for (int o = 16; o > 0; o >>= 1) s += __shfl_xor_sync(0xFFFFFFFF, s, o);
    if (lane == 0) g_ball[w] = s;
}
__global__ void bias_copy_kernel(const float* __restrict__ bu, const float* __restrict__ bo) {
    int n = 2048 + blockIdx.x * blockDim.x + threadIdx.x;
    if (n < 3072) g_ball[n] = bu[n - 2048];
    else if (n < 4096) g_ball[n] = bo[n - 3072];
}
__global__ void wb_rows_kernel(const float* __restrict__ wfw, const float* __restrict__ wiw) {
    int i16 = blockIdx.y;
    int d = blockIdx.x * 256 + threadIdx.x;
    int g = i16 >> 3, i = i16 & 7;
    const float* ww = g ? wiw : wfw;
    float s = 0.f;
    for (int j = 0; j < 1024; j++)
        s += __ldg(&ww[i * 1024 + j]) * g_Wall[(size_t)(g * 1024 + j) * DD + d];
    g_Wall[(size_t)(4096 + i16) * DD + d] = s;
}
__global__ void bias_wb_kernel(const float* __restrict__ wfw, const float* __restrict__ wiw) {
    int w = threadIdx.x >> 5, lane = threadIdx.x & 31;
    if (w >= 16) return;
    int g = w >> 3, i = w & 7;
    const float* ww = g ? wiw : wfw;
    const float* bb = g_ball + g * 1024;
    float s = 0.f;
    for (int j = lane; j < 1024; j += 32) s += ww[i * 1024 + j] * bb[j];
#pragma unroll
    for (int o = 16; o > 0; o >>= 1) s += __shfl_xor_sync(0xFFFFFFFF, s, o);
    if (lane == 0) g_ball[4096 + w] = s;
}
// permute bias: ballp[n'] = ball[orig(n')]
__global__ void ballp_kernel() {
    int n = blockIdx.x * blockDim.x + threadIdx.x;
    if (n >= NPAD) return;
    float v = 0.f;
    if (n < 16) v = g_ball[4096 + n];
    else if (n < 4112) {
        int g = (n - 16) & 3, h = (n - 16) >> 2;
        v = g_ball[g * 1024 + h];
    }
    g_ballp[n] = v;
}
// B matrices with permuted rows: Bpx[n'][k] = Wall[orig(n')][k], Bph = cols 1024..2047
__global__ void bsplit_kernel() {
    size_t idx = (size_t)blockIdx.x * blockDim.x + threadIdx.x;
    if (idx >= (size_t)NPAD * 2048) return;
    int n = (int)(idx / 2048), c = (int)(idx % 2048);
    float v = 0.f;
    if (n < 16) v = g_Wall[(size_t)(4096 + n) * DD + c];
    else if (n < 4112) {
        int g = (n - 16) & 3, h = (n - 16) >> 2;
        v = g_Wall[(size_t)(g * 1024 + h) * DD + c];
    }
    if (c < 1024) g_Bpx[(size_t)n * 1024 + c] = __float2half(v);
    else          g_Bph[(size_t)n * 1024 + (c - 1024)] = __float2half(v);
}
__global__ void xprep_kernel(const float* __restrict__ X) {
    size_t idx = (size_t)blockIdx.x * blockDim.x + threadIdx.x;
    if (idx < (size_t)T_STEPS * BB * 1024)
        g_Xp[idx] = __float2half(X[idx]);
}

// ============================================================
// host
// ============================================================
extern "C" void kernel_launch(void* const* d_in, const int* in_sizes, int n_in,
                              void* d_out, int out_size)
{
    const float* X    = (const float*)d_in[0];
    const float* Wq   = (const float*)d_in[1];
    const float* bq   = (const float*)d_in[2];
    const float* encf = (const float*)d_in[3];
    const float* wfw  = (const float*)d_in[4];
    const float* wfb  = (const float*)d_in[5];
    const float* enci = (const float*)d_in[6];
    const float* wiw  = (const float*)d_in[7];
    const float* wib  = (const float*)d_in[8];
    const float* Wu   = (const float*)d_in[9];
    const float* bu   = (const float*)d_in[10];
    const float* Wo   = (const float*)d_in[11];
    const float* bo   = (const float*)d_in[12];
    float* out = (float*)d_out;

    static bool attr_done = false;
    if (!attr_done) {
        cudaFuncSetAttribute(persist_kernel, cudaFuncAttributeMaxDynamicSharedMemorySize, GSMEM);
        cudaFuncSetAttribute(xpre_kernel, cudaFuncAttributeMaxDynamicSharedMemorySize, XP_SMEM);
        cudaFuncSetAttribute(prep_mma_kernel, cudaFuncAttributeMaxDynamicSharedMemorySize, XP_SMEM);
        attr_done = true;
    }

    // ---- prep ----
    init_state_kernel<<<(HH * BB + 255) / 256, 256>>>();
    {
        size_t total = (size_t)2 * 1024 * DD;
        copy_wuwo_kernel<<<(unsigned)((total + 255) / 256), 256>>>(Wu, Wo);
    }
    enc16_kernel<<<(1024 * 1024 + 255) / 256, 256>>>(encf, enci);
    wqt_kernel<<<dim3(64, 32), dim3(32, 8)>>>(Wq);
    prep_mma_kernel<<<dim3(16, 4, 2), 256, XP_SMEM>>>();
    bias_enc_kernel<<<256, 256>>>(encf, enci, bq);
    bias_copy_kernel<<<8, 256>>>(bu, bo);
    wb_rows_kernel<<<dim3(8, 16), 256>>>(wfw, wiw);
    bias_wb_kernel<<<1, 512>>>(wfw, wiw);
    ballp_kernel<<<(NPAD + 255) / 256, 256>>>();
    {
        size_t total = (size_t)NPAD * 2048;
        bsplit_kernel<<<(unsigned)((total + 255) / 256), 256>>>();
    }
    {
        size_t total = (size_t)T_STEPS * BB * 1024;
        xprep_kernel<<<(unsigned)((total + 255) / 256), 256>>>(X);
    }

    // ---- X precompute: one big GEMM for all timesteps (permuted cols) ----
    xpre_kernel<<<dim3(33, T_STEPS), 256, XP_SMEM>>>();

    // ---- recurrence: persistent H-GEMM + CTA-local elem, 1 bar/step ----
    dim3 grid_step(33, 4);   // 132 CTAs, all resident
    persist_kernel<<<grid_step, 384, GSMEM>>>(out, wfw, wfb, wiw, wib);
}